// round 13
// baseline (speedup 1.0000x reference)
#include <cuda_runtime.h>
#include <cstdint>

// Transformer_66529043415377 — persistent-CTA async-bulk zero stores, v3.
//
// Reference quirks: y clamped to [0, C-1]=[0,2], x to [0, H-1]=[0,511],
// raw [N,3] channel-interleaved output.
//
// Exact-zero structure (bit-exact since R2): with the reference's rounding
// order a pixel is nonzero ONLY when y = h + 64*dy lies in [0,2). Otherwise
// both clamped rows coincide, wb=-wa, wd=-wc exactly, and the left-assoc
// sum cancels to +0.0.
//
// R13 design: the SMEM zero buffer is filled ONCE per CTA and reused as the
// source of T bulk stores (it is never dirtied — patches go straight to
// GMEM). Zero path per tile: dy prefetch LDG + bulk issue + syncthreads_or.
// No per-tile STS, no per-tile drain wait; bulk ops pipeline on the async
// engines and backpressure at the L2 cap (the actual roofline, ~5.6 us for
// 67 MB). wait_group 0 only when patching and once before CTA exit.

namespace {
constexpr int B  = 16;
constexpr int H  = 512;
constexpr int W  = 512;
constexpr int HW = H * W;             // 262144
constexpr int N  = B * HW;            // 4194304 pixels
constexpr int THREADS = 256;
constexpr int PIX = 4;
constexpr int TILE_PX    = THREADS * PIX;      // 1024
constexpr int TILE_BYTES = TILE_PX * 3 * 4;    // 12288
constexpr int T = 4;                           // tiles per CTA
constexpr int CTAS = N / (TILE_PX * T);        // 1024
}

__device__ __forceinline__ uint32_t smem_u32(const void* p) {
    uint32_t a;
    asm("{ .reg .u64 t; cvta.to.shared.u64 t, %1; cvt.u32.u64 %0, t; }"
        : "=r"(a) : "l"(p));
    return a;
}

__global__ __launch_bounds__(THREADS)
void transformer_warp_kernel(const float* __restrict__ flow,
                             const float* __restrict__ pqf,
                             float* __restrict__ out)
{
    __shared__ float4 zbuf[TILE_BYTES / 16];   // 12 KB of zeros, written ONCE

    const int tid = threadIdx.x;

    // One-time zero fill (3 STS.128 per thread).
    const float4 z = make_float4(0.0f, 0.0f, 0.0f, 0.0f);
    zbuf[tid]       = z;
    zbuf[tid + 256] = z;
    zbuf[tid + 512] = z;
    __syncthreads();
    if (tid == 0)
        asm volatile("fence.proxy.async.shared::cta;" ::: "memory");

    const uint32_t saddr = smem_u32(zbuf);

    const int tile0 = blockIdx.x * T;
    const int i0    = tile0 * TILE_PX;          // CTA's first pixel
    const int b     = i0 >> 18;                 // batch const per CTA (4096-px range)
    const int baseb = b << 9;                   // b * dim1 (=W=512)
    const float* fb0 = flow + (size_t)b * 2 * HW;   // batch flow base

    // Prefetch dy for tile 0.
    int rem = (i0 + tid * PIX) & (HW - 1);
    float4 dy_next = *reinterpret_cast<const float4*>(fb0 + HW + rem);

#pragma unroll
    for (int k = 0; k < T; ++k) {
        const int i   = (tile0 + k) * TILE_PX + tid * PIX;
        const int remk = i & (HW - 1);
        const int h   = remk >> 9;
        const int w   = remk & (W - 1);

        const float4 dy4 = dy_next;
        // Prefetch next tile's dy so it flies across this tile's work.
        if (k + 1 < T) {
            const int remn = ((tile0 + k + 1) * TILE_PX + tid * PIX) & (HW - 1);
            dy_next = *reinterpret_cast<const float4*>(fb0 + HW + remn);
        }

        // Issue the bulk zero store for this tile (source = pristine zbuf).
        if (tid == 0) {
            const float* gdst = out + (size_t)(tile0 + k) * TILE_PX * 3;
            asm volatile(
                "cp.async.bulk.global.shared::cta.bulk_group [%0], [%1], %2;"
                :: "l"(gdst), "r"(saddr), "r"(TILE_BYTES) : "memory");
            asm volatile("cp.async.bulk.commit_group;" ::: "memory");
        }

        const float yf = (float)h;
        // fmaf bit-exact: dy*64 exact (power-of-two scale)
        const float y0 = __fmaf_rn(dy4.x, 64.0f, yf);
        const float y1 = __fmaf_rn(dy4.y, 64.0f, yf);
        const float y2 = __fmaf_rn(dy4.z, 64.0f, yf);
        const float y3 = __fmaf_rn(dy4.w, 64.0f, yf);

        const bool a0 = (y0 >= 0.0f) && (y0 < 2.0f);
        const bool a1 = (y1 >= 0.0f) && (y1 < 2.0f);
        const bool a2 = (y2 >= 0.0f) && (y2 < 2.0f);
        const bool a3 = (y3 >= 0.0f) && (y3 < 2.0f);
        const bool any = a0 | a1 | a2 | a3;

        const int cta_any = __syncthreads_or((int)any);

        if (cta_any) {
            // Drain all pending bulk stores (incl. this tile), then patch.
            if (tid == 0)
                asm volatile("cp.async.bulk.wait_group 0;" ::: "memory");
            __syncthreads();

            if (any) {
                const float4 dx4 = *reinterpret_cast<const float4*>(fb0 + remk);
                const float dxs[4] = {dx4.x, dx4.y, dx4.z, dx4.w};
                const float yv[4]  = {y0, y1, y2, y3};
                const bool  act[4] = {a0, a1, a2, a3};

#pragma unroll
                for (int j = 0; j < 4; ++j) {
                    if (!act[j]) continue;

                    const float y = yv[j];
                    const float x = __fmaf_rn(dxs[j], 64.0f, (float)(w + j));

                    float x0f = floorf(x);
                    float x1f = __fadd_rn(x0f, 1.0f);
                    x0f = fminf(fmaxf(x0f, 0.0f), 511.0f);  // max_x = H-1
                    x1f = fminf(fmaxf(x1f, 0.0f), 511.0f);

                    // active => y in [0,2): clamps no-ops; equals ref's y0,y1
                    const float y0f = floorf(y);
                    const float y1f = __fadd_rn(y0f, 1.0f);

                    const int ix0 = (int)x0f;
                    const int ix1 = (int)x1f;
                    const int iy0 = (int)y0f;
                    const int iy1 = (int)y1f;

                    const int idx_a = baseb + iy0 * HW + ix0;
                    const int idx_b = baseb + iy1 * HW + ix0;
                    const int idx_c = baseb + iy0 * HW + ix1;
                    const int idx_d = baseb + iy1 * HW + ix1;

                    // single-rounded weight products (no fma pattern)
                    const float wxa = __fsub_rn(x1f, x);
                    const float wxc = __fsub_rn(x, x0f);
                    const float wya = __fsub_rn(y1f, y);
                    const float wyb = __fsub_rn(y, y0f);
                    const float wa = __fmul_rn(wxa, wya);
                    const float wb = __fmul_rn(wxa, wyb);
                    const float wc = __fmul_rn(wxc, wya);
                    const float wd = __fmul_rn(wxc, wyb);

                    const float* pa = pqf + (size_t)idx_a * 3;
                    const float* pb = pqf + (size_t)idx_b * 3;
                    const float* pc = pqf + (size_t)idx_c * 3;
                    const float* pd = pqf + (size_t)idx_d * 3;

                    float* op = out + (size_t)(i + j) * 3;
#pragma unroll
                    for (int c = 0; c < 3; ++c) {
                        // exact reference order: ((wa*A + wb*B) + wc*C) + wd*D
                        const float pA = __fmul_rn(wa, __ldg(pa + c));
                        const float pB = __fmul_rn(wb, __ldg(pb + c));
                        const float pC = __fmul_rn(wc, __ldg(pc + c));
                        const float pD = __fmul_rn(wd, __ldg(pd + c));
                        op[c] = __fadd_rn(__fadd_rn(__fadd_rn(pA, pB), pC), pD);
                    }
                }
            }
        }
    }

    // SMEM-reuse safety: pending bulk ops read zbuf; do not exit until
    // drained (a successor CTA could overwrite the source mid-copy).
    if (tid == 0)
        asm volatile("cp.async.bulk.wait_group 0;" ::: "memory");
}

extern "C" void kernel_launch(void* const* d_in, const int* in_sizes, int n_in,
                              void* d_out, int out_size)
{
    const float* flow = (const float*)d_in[0];
    const float* pqf  = (const float*)d_in[1];
    float* out        = (float*)d_out;

    transformer_warp_kernel<<<CTAS, THREADS>>>(flow, pqf, out);
}

// round 14
// speedup vs baseline: 1.2343x; 1.2343x over previous
#include <cuda_runtime.h>
#include <cstdint>

// Transformer_66529043415377 — fused kernel, async-bulk zero stores, v4.
//
// Reference quirks: y clamped to [0, C-1]=[0,2], x to [0, H-1]=[0,511],
// raw [N,3] channel-interleaved output.
//
// Exact-zero structure (bit-exact since R2): with the reference's rounding
// order a pixel is nonzero ONLY when y = h + 64*dy lies in [0,2). Otherwise
// both clamped rows coincide, wb=-wa, wd=-wc exactly, and the left-assoc
// sum cancels to +0.0.
//
// R14 change vs R12 (13.2 us): drop the CTA-exit wait_group. Rationale:
// the only hazard it guarded was a successor CTA overwriting zbuf while
// this CTA's bulk store still reads it — but every CTA writes the SAME
// zeros at the SAME static SMEM offsets, so the race is value-free: the
// bulk engine reads 0x00 bytes either way. Removing the wait takes the
// ~600-cycle drain off every CTA's warp-0 lifetime and recycles CTA slots
// faster. The patch path KEEPS wait_group 0 + barrier (zeros must land
// before patch STGs to the same lines).

namespace {
constexpr int B  = 16;
constexpr int H  = 512;
constexpr int W  = 512;
constexpr int HW = H * W;            // 262144
constexpr int N  = B * HW;           // 4194304 pixels
constexpr int PIX = 4;
constexpr int THREADS = 128;
constexpr int PX_PER_CTA = PIX * THREADS;         // 512
constexpr int BYTES_PER_CTA = PX_PER_CTA * 3 * 4; // 6144
}

__device__ __forceinline__ uint32_t smem_u32(const void* p) {
    uint32_t a;
    asm("{ .reg .u64 t; cvta.to.shared.u64 t, %1; cvt.u32.u64 %0, t; }"
        : "=r"(a) : "l"(p));
    return a;
}

__global__ __launch_bounds__(THREADS)
void transformer_warp_kernel(const float* __restrict__ flow,
                             const float* __restrict__ pqf,
                             float* __restrict__ out)
{
    __shared__ float4 zbuf[BYTES_PER_CTA / 16];  // 6 KB of zeros

    const int tid = threadIdx.x;

    const int t = blockIdx.x * THREADS + tid;
    const int i = t * PIX;                      // base pixel index

    const int b   = i >> 18;                    // / HW
    const int rem = i & (HW - 1);
    const int h   = rem >> 9;                   // / W
    const int w   = rem & (W - 1);

    // Issue the dy load FIRST so it flies across the barrier + bulk issue.
    const float* fbase = flow + (size_t)b * 2 * HW + rem;
    const float4 dy4 = *reinterpret_cast<const float4*>(fbase + HW);

    // Zero the SMEM tile (3 STS.128 per thread).
    const float4 z = make_float4(0.0f, 0.0f, 0.0f, 0.0f);
    zbuf[tid]       = z;
    zbuf[tid + 128] = z;
    zbuf[tid + 256] = z;

    __syncthreads();                            // STS complete -> bulk may read

    // One bulk store of the CTA's whole 6 KB output span (async proxy,
    // bypasses L1). Issued before dy is consumed: drain overlaps compute.
    if (tid == 0) {
        asm volatile("fence.proxy.async.shared::cta;" ::: "memory");
        const uint32_t saddr = smem_u32(zbuf);
        const float*   gdst  = out + (size_t)blockIdx.x * (BYTES_PER_CTA / 4);
        asm volatile(
            "cp.async.bulk.global.shared::cta.bulk_group [%0], [%1], %2;"
            :: "l"(gdst), "r"(saddr), "r"(BYTES_PER_CTA) : "memory");
        asm volatile("cp.async.bulk.commit_group;" ::: "memory");
    }

    const float yf = (float)h;

    // fmaf bit-exact: dy*64 exact (power-of-two scale)
    const float y0 = __fmaf_rn(dy4.x, 64.0f, yf);
    const float y1 = __fmaf_rn(dy4.y, 64.0f, yf);
    const float y2 = __fmaf_rn(dy4.z, 64.0f, yf);
    const float y3 = __fmaf_rn(dy4.w, 64.0f, yf);

    const bool a0 = (y0 >= 0.0f) && (y0 < 2.0f);
    const bool a1 = (y1 >= 0.0f) && (y1 < 2.0f);
    const bool a2 = (y2 >= 0.0f) && (y2 < 2.0f);
    const bool a3 = (y3 >= 0.0f) && (y3 < 2.0f);
    const bool any = a0 | a1 | a2 | a3;

    // Race-free block-wide OR.
    const int cta_any = __syncthreads_or((int)any);

    // NO exit wait: a successor CTA reusing this SMEM writes the same zeros
    // to the same offsets, so an in-flight bulk read observes identical
    // bytes. (Value-free race — see header comment.)
    if (cta_any == 0) return;

    // Patch ordering: zeros must fully land before patch STGs.
    if (tid == 0)
        asm volatile("cp.async.bulk.wait_group 0;" ::: "memory");
    __syncthreads();
    if (!any) return;

    // Rare path: patch active pixels over the zeros (bit-exact ref order).
    const float4 dx4 = *reinterpret_cast<const float4*>(fbase);
    const float dxs[4] = {dx4.x, dx4.y, dx4.z, dx4.w};
    const float yv[4]  = {y0, y1, y2, y3};
    const bool  act[4] = {a0, a1, a2, a3};

    const int baseb = b << 9;                   // b * dim1 (=W=512)

#pragma unroll
    for (int j = 0; j < 4; ++j) {
        if (!act[j]) continue;

        const float y = yv[j];
        const float x = __fmaf_rn(dxs[j], 64.0f, (float)(w + j)); // bit-exact

        float x0f = floorf(x);
        float x1f = __fadd_rn(x0f, 1.0f);
        x0f = fminf(fmaxf(x0f, 0.0f), 511.0f);  // max_x = H-1 = 511
        x1f = fminf(fmaxf(x1f, 0.0f), 511.0f);

        // active => y in [0,2): clamps no-ops; equals reference's y0,y1
        const float y0f = floorf(y);
        const float y1f = __fadd_rn(y0f, 1.0f);

        const int ix0 = (int)x0f;
        const int ix1 = (int)x1f;
        const int iy0 = (int)y0f;
        const int iy1 = (int)y1f;

        const int idx_a = baseb + iy0 * HW + ix0;
        const int idx_b = baseb + iy1 * HW + ix0;
        const int idx_c = baseb + iy0 * HW + ix1;
        const int idx_d = baseb + iy1 * HW + ix1;

        // single-rounded weight products (no contractible fma pattern)
        const float wxa = __fsub_rn(x1f, x);
        const float wxc = __fsub_rn(x, x0f);
        const float wya = __fsub_rn(y1f, y);
        const float wyb = __fsub_rn(y, y0f);
        const float wa = __fmul_rn(wxa, wya);
        const float wb = __fmul_rn(wxa, wyb);
        const float wc = __fmul_rn(wxc, wya);
        const float wd = __fmul_rn(wxc, wyb);

        const float* pa = pqf + (size_t)idx_a * 3;
        const float* pb = pqf + (size_t)idx_b * 3;
        const float* pc = pqf + (size_t)idx_c * 3;
        const float* pd = pqf + (size_t)idx_d * 3;

        float* op = out + (size_t)(i + j) * 3;
#pragma unroll
        for (int c = 0; c < 3; ++c) {
            // exact reference order: ((wa*A + wb*B) + wc*C) + wd*D,
            // each product individually rounded, no contraction
            const float pA = __fmul_rn(wa, __ldg(pa + c));
            const float pB = __fmul_rn(wb, __ldg(pb + c));
            const float pC = __fmul_rn(wc, __ldg(pc + c));
            const float pD = __fmul_rn(wd, __ldg(pd + c));
            op[c] = __fadd_rn(__fadd_rn(__fadd_rn(pA, pB), pC), pD);
        }
    }
}

extern "C" void kernel_launch(void* const* d_in, const int* in_sizes, int n_in,
                              void* d_out, int out_size)
{
    const float* flow = (const float*)d_in[0];
    const float* pqf  = (const float*)d_in[1];
    float* out        = (float*)d_out;

    const int blocks = N / PX_PER_CTA;          // 8192
    transformer_warp_kernel<<<blocks, THREADS>>>(flow, pqf, out);
}